// round 11
// baseline (speedup 1.0000x reference)
#include <cuda_runtime.h>
#include <cuda_fp16.h>
#include <cstdint>
#include <cstddef>

// ============================================================================
// Problem constants
// ============================================================================
#define HDIM 4096
#define BDIM 4096
static constexpr size_t BH_ = (size_t)HDIM * (size_t)BDIM;   // 16777216

// ============================================================================
// Device scratch.
//   g_act slots 0..3: xk/xv/xr/g — fp16 FRAGMENT-MAJOR: [B/16][H/16] frags of
//     256 fp16 (= 32 uint4; ONE uint4 per lane). Lane L holds the mma
//     m16n8k16 A-frag register image:
//       r=L/4, c=(L%4)*2 -> h[0..7] = (r,c),(r,c+1),(r+8,c),(r+8,c+1),
//                                     (r,c+8),(r,c+9),(r+8,c+8),(r+8,c+9)
//   g_wt  slots 0..3: Wk^T/Wv^T/Wr^T/Wo^T fp16 [N,K] K-major
//   g_lin slots 0..2: k/v/r fp32 [B,H] normal layout
// ============================================================================
__device__ __align__(128) __half g_act[4 * BH_];
__device__ __align__(128) __half g_wt[4 * BH_];
__device__ __align__(128) float  g_lin[3 * BH_];

__device__ __forceinline__ uint32_t smem_u32(const void* p) {
    uint32_t a;
    asm("{ .reg .u64 t; cvta.to.shared.u64 t, %1; cvt.u32.u64 %0, t; }"
        : "=r"(a) : "l"(p));
    return a;
}

#define SWZ(o) ((o) ^ (((o) >> 3) & 0x70))

#define CP_ASYNC16(sa, ga)                                                     \
    asm volatile("cp.async.cg.shared.global [%0], [%1], 16;"                   \
                 :: "r"(sa), "l"(ga))

#define MBAR_INIT(addr, cnt)                                                   \
    asm volatile("mbarrier.init.shared.b64 [%0], %1;"                          \
                 :: "r"(addr), "r"(cnt) : "memory")
#define MBAR_ARRIVE(addr)                                                      \
    asm volatile("mbarrier.arrive.shared.b64 _, [%0];"                         \
                 :: "r"(addr) : "memory")
#define CPASYNC_MBAR_ARRIVE(addr)                                              \
    asm volatile("cp.async.mbarrier.arrive.noinc.shared.b64 [%0];"             \
                 :: "r"(addr) : "memory")

#define MBAR_WAIT(addr, ph) do {                                               \
    uint32_t _m = (uint32_t)(addr), _p = (uint32_t)(ph), _d;                   \
    asm volatile(                                                              \
        "{\n\t.reg .pred p;\n\t"                                               \
        "mbarrier.try_wait.parity.acquire.cta.shared::cta.b64 p, [%1], %2;\n\t"\
        "selp.b32 %0, 1, 0, p;\n\t}"                                           \
        : "=r"(_d) : "r"(_m), "r"(_p) : "memory");                             \
    if (!_d) {                                                                 \
        asm volatile(                                                          \
            "{\n\t.reg .pred P1;\n\t"                                          \
            "WL%=:\n\t"                                                        \
            "mbarrier.try_wait.parity.acquire.cta.shared::cta.b64 P1, [%0], %1, 0x989680;\n\t" \
            "@P1 bra.uni WD%=;\n\t"                                            \
            "bra.uni WL%=;\n\t"                                                \
            "WD%=:\n\t}"                                                       \
            :: "r"(_m), "r"(_p) : "memory");                                   \
    }                                                                          \
} while (0)

#define LDSM_X4(r0, r1, r2, r3, addr)                                          \
    asm volatile("ldmatrix.sync.aligned.m8n8.x4.shared.b16 {%0,%1,%2,%3}, [%4];" \
                 : "=r"(r0), "=r"(r1), "=r"(r2), "=r"(r3) : "r"(addr))

#define MMA16816(c, a, b0, b1)                                                 \
    asm volatile("mma.sync.aligned.m16n8k16.row.col.f32.f16.f16.f32 "          \
                 "{%0,%1,%2,%3}, {%4,%5,%6,%7}, {%8,%9}, {%0,%1,%2,%3};"       \
                 : "+f"((c)[0]), "+f"((c)[1]), "+f"((c)[2]), "+f"((c)[3])      \
                 : "r"((a)[0]), "r"((a)[1]), "r"((a)[2]), "r"((a)[3]),         \
                   "r"(b0), "r"(b1))

// ============================================================================
// HGEMM: C = A @ B^T. A fp16 fragment-major (direct LDG.128, NO smem),
// B fp16 [N,K] K-major via cp.async + mbarrier ring + LDSM (r7 path).
// CTA tile 128x128, BK=64, 4 warps 64x64, occ 2.
// ============================================================================
#define BM 128
#define BN 128
#define BK 64
#define GTHREADS 128
#define NKITERS (HDIM / BK)                 // 64
#define STAGE_BYTES (BN * 128)              // 16384 (B only)
#define SM_TILE0 1024
#define GSMEM (SM_TILE0 + 3 * STAGE_BYTES)  // 50176
#define HBLK (HDIM / 16)                    // 256 k-blocks per row-panel
#define FRAG_U4 32                          // uint4 per 16x16 fragment

__global__ void __launch_bounds__(GTHREADS, 2)
hgemm_kernel(float* __restrict__ Cout, int mode)
{
    extern __shared__ char smem[];
    const uint32_t sb = smem_u32(smem);
    const int tid = threadIdx.x;
    const int wid = tid >> 5;
    const int lane = tid & 31;

    const int z = (mode == 0) ? (int)blockIdx.z : 3;
    const __half* __restrict__ Bw = g_wt + (size_t)z * BH_;
    float* __restrict__ C = (mode == 0) ? (g_lin + (size_t)z * BH_) : Cout;

    // ---- CTA swizzle: 16-wide x-groups ----
    const int bidlin = (int)(blockIdx.x + gridDim.x * blockIdx.y);
    const int per = 16 * (int)gridDim.y;
    const int grp = bidlin / per;
    const int rem = bidlin - grp * per;
    const int m0 = (rem / 16) * BM;
    const int n0 = (grp * 16 + (rem % 16)) * BN;

    if (tid == 0) {
        #pragma unroll
        for (int s = 0; s < 3; s++) {
            MBAR_INIT(sb + s * 16, GTHREADS);
            MBAR_INIT(sb + s * 16 + 8, GTHREADS);
        }
    }
    __syncthreads();

    // ---- B cp.async bases (rows n0..n0+127) ----
    const int lrow = tid >> 3, lcol = tid & 7;
    const __half* gBb = Bw + (size_t)(n0 + lrow) * HDIM + lcol * 8;
    const uint32_t sBb = sb + SM_TILE0 + SWZ((uint32_t)(lrow * 128 + lcol * 16));

    #define LOAD_STAGE(slot, kc) do {                                          \
        uint32_t off = (uint32_t)(slot) * STAGE_BYTES;                         \
        size_t ko = (size_t)(kc) * BK;                                         \
        _Pragma("unroll")                                                      \
        for (int c = 0; c < 8; c++)                                            \
            CP_ASYNC16(sBb + off + c * 2048, gBb + ko + (size_t)c * 16 * HDIM);\
    } while (0)

    // ---- warp tiling: 2x2 warps, each 64x64 ----
    const int wm = (wid & 1) * 64;
    const int wn = (wid >> 1) * 64;
    const uint32_t xorv = (uint32_t)((lane & 7) << 4);
    const uint32_t bcol0 = (uint32_t)((lane >> 4) << 4);
    uint32_t rowBoff[4];
    #pragma unroll
    for (int nt2 = 0; nt2 < 4; nt2++)
        rowBoff[nt2] = (uint32_t)(SM_TILE0 + (wn + nt2 * 16 + (lane & 15)) * 128);

    // ---- A fragment pointers (fragment-major gmem; one uint4 per frag/lane)
    const int mbase = (m0 + wm) >> 4;
    const uint4* aPtr[4];
    #pragma unroll
    for (int mt = 0; mt < 4; mt++)
        aPtr[mt] = (const uint4*)(g_act + (size_t)z * BH_)
                 + (size_t)(mbase + mt) * HBLK * FRAG_U4 + lane;

    float acc[4][8][4];
    #pragma unroll
    for (int mt = 0; mt < 4; mt++)
        #pragma unroll
        for (int nt = 0; nt < 8; nt++)
            #pragma unroll
            for (int e = 0; e < 4; e++) acc[mt][nt][e] = 0.0f;

    // ---- A register ring: 4 slots x 4 mt frags; prefetch depth 2 ks-steps
    uint4 aring[4][4];
    #pragma unroll
    for (int mt = 0; mt < 4; mt++) {
        aring[0][mt] = aPtr[mt][0];
        aring[1][mt] = aPtr[mt][FRAG_U4];        // kb=1
    }

    // ---- B prologue: stages 0,1 ----
    LOAD_STAGE(0, 0);
    CPASYNC_MBAR_ARRIVE(sb + 0 * 16);
    LOAD_STAGE(1, 1);
    CPASYNC_MBAR_ARRIVE(sb + 1 * 16);

    for (int kc = 0; kc < NKITERS; kc++) {
        const int s = kc - (kc / 3) * 3;
        const int t = kc + 2;
        if (t < NKITERS) {
            const int s2 = t - (t / 3) * 3;
            if (t >= 3)
                MBAR_WAIT(sb + s2 * 16 + 8, ((t - 3) / 3) & 1);
            LOAD_STAGE(s2, t);
            CPASYNC_MBAR_ARRIVE(sb + s2 * 16);
        }
        MBAR_WAIT(sb + s * 16, (kc / 3) & 1);

        const uint32_t sbase = sb + (uint32_t)s * STAGE_BYTES;
        #pragma unroll
        for (int ks = 0; ks < 4; ks++) {
            // prefetch A for ks+2 (may cross into next chunk — gmem, no sync)
            const int kbp = kc * 4 + ks + 2;
            if (kbp < 4 * NKITERS) {
                #pragma unroll
                for (int mt = 0; mt < 4; mt++)
                    aring[(ks + 2) & 3][mt] = aPtr[mt][(size_t)kbp * FRAG_U4];
            }
            // B frags for this ks
            uint32_t bf[4][4];
            const uint32_t bc = ((uint32_t)(ks * 32) + bcol0) ^ xorv;
            #pragma unroll
            for (int nt2 = 0; nt2 < 4; nt2++)
                LDSM_X4(bf[nt2][0], bf[nt2][1], bf[nt2][2], bf[nt2][3],
                        sbase + rowBoff[nt2] + bc);
            #pragma unroll
            for (int mt = 0; mt < 4; mt++) {
                const uint32_t* a = (const uint32_t*)&aring[ks][mt];
                #pragma unroll
                for (int nt = 0; nt < 8; nt++) {
                    uint32_t b0 = (nt & 1) ? bf[nt >> 1][1] : bf[nt >> 1][0];
                    uint32_t b1 = (nt & 1) ? bf[nt >> 1][3] : bf[nt >> 1][2];
                    MMA16816(acc[mt][nt], a, b0, b1);
                }
            }
        }
        MBAR_ARRIVE(sb + s * 16 + 8);
    }

    // ---- epilogue ----
    const int gr = lane >> 2;
    const int gc = (lane & 3) * 2;
    #pragma unroll
    for (int mt = 0; mt < 4; mt++) {
        #pragma unroll
        for (int nt = 0; nt < 8; nt++) {
            int row = m0 + wm + mt * 16 + gr;
            int col = n0 + wn + nt * 8 + gc;
            float2 v0 = make_float2(acc[mt][nt][0], acc[mt][nt][1]);
            float2 v1 = make_float2(acc[mt][nt][2], acc[mt][nt][3]);
            *(float2*)(C + (size_t)row * HDIM + col) = v0;
            *(float2*)(C + (size_t)(row + 8) * HDIM + col) = v1;
        }
    }
    #undef LOAD_STAGE
}

// ============================================================================
// Fragment packing helper
// ============================================================================
__device__ __forceinline__ uint4 pack8h(float v0, float v1, float v2, float v3,
                                        float v4, float v5, float v6, float v7)
{
    union { __half h[8]; uint4 u; } u;
    u.h[0] = __float2half_rn(v0); u.h[1] = __float2half_rn(v1);
    u.h[2] = __float2half_rn(v2); u.h[3] = __float2half_rn(v3);
    u.h[4] = __float2half_rn(v4); u.h[5] = __float2half_rn(v5);
    u.h[6] = __float2half_rn(v6); u.h[7] = __float2half_rn(v7);
    return u.u;
}

// ============================================================================
// Fused prep: weight transpose (normal) + token-shift mix (fragment-major).
// ============================================================================
#define WSPLIT_BLOCKS (4 * (HDIM / 32) * (HDIM / 32))   // 65536
#define MIX_BLOCKS ((int)(BH_ / 256 / 8))               // 8192

__global__ void prep_kernel(const float* __restrict__ W0, const float* __restrict__ W1,
                            const float* __restrict__ W2, const float* __restrict__ W3,
                            const float* __restrict__ x, const float* __restrict__ sx,
                            const float* __restrict__ km, const float* __restrict__ vm,
                            const float* __restrict__ rm, float* __restrict__ out_x,
                            int do_copy)
{
    __shared__ float tile[32][33];
    int b = (int)blockIdx.x;
    if (b < WSPLIT_BLOCKS) {
        const int z = b >> 14;
        const int r = b & 16383;
        const int n0 = (r & 127) * 32;
        const int k0 = (r >> 7) * 32;
        const float* W = (z == 0) ? W0 : (z == 1) ? W1 : (z == 2) ? W2 : W3;
        const int tx = threadIdx.x & 31, ty = threadIdx.x >> 5;

        #pragma unroll
        for (int i = 0; i < 4; i++)
            tile[ty + 8 * i][tx] = W[(size_t)(k0 + ty + 8 * i) * HDIM + (n0 + tx)];
        __syncthreads();

        const size_t base = (size_t)z * BH_;
        #pragma unroll
        for (int i = 0; i < 4; i++) {
            float v = tile[tx][ty + 8 * i];
            g_wt[base + (size_t)(n0 + ty + 8 * i) * HDIM + (k0 + tx)] = __float2half_rn(v);
        }
    } else {
        // ---- mix: warp w handles frag f = (b-W)*8 + w ----
        const int f = (b - WSPLIT_BLOCKS) * 8 + (threadIdx.x >> 5);
        const int lane = threadIdx.x & 31;
        const int row0 = (f >> 8) * 16 + (lane >> 2);       // bblk*16 + r
        const int col0 = (f & 255) * 16 + ((lane & 3) << 1);// hblk*16 + c

        const size_t p00 = (size_t)row0 * HDIM + col0;
        const size_t p10 = p00 + 8 * HDIM;
        float2 x00 = *(const float2*)(x + p00), s00 = *(const float2*)(sx + p00);
        float2 x10 = *(const float2*)(x + p10), s10 = *(const float2*)(sx + p10);
        float2 x01 = *(const float2*)(x + p00 + 8), s01 = *(const float2*)(sx + p00 + 8);
        float2 x11 = *(const float2*)(x + p10 + 8), s11 = *(const float2*)(sx + p10 + 8);

        int h = col0 & (HDIM - 1);
        float2 kma = *(const float2*)(km + h), kmb = *(const float2*)(km + h + 8);
        float2 vma = *(const float2*)(vm + h), vmb = *(const float2*)(vm + h + 8);
        float2 rma = *(const float2*)(rm + h), rmb = *(const float2*)(rm + h + 8);

        if (do_copy) {
            *(float2*)(out_x + p00) = x00;
            *(float2*)(out_x + p10) = x10;
            *(float2*)(out_x + p00 + 8) = x01;
            *(float2*)(out_x + p10 + 8) = x11;
        }
        uint4* dst0 = (uint4*)g_act + (size_t)f * FRAG_U4 + lane;
        #define MIXV(ma, mb)                                                   \
            pack8h(fmaf(ma.x, x00.x - s00.x, s00.x), fmaf(ma.y, x00.y - s00.y, s00.y), \
                   fmaf(ma.x, x10.x - s10.x, s10.x), fmaf(ma.y, x10.y - s10.y, s10.y), \
                   fmaf(mb.x, x01.x - s01.x, s01.x), fmaf(mb.y, x01.y - s01.y, s01.y), \
                   fmaf(mb.x, x11.x - s11.x, s11.x), fmaf(mb.y, x11.y - s11.y, s11.y))
        dst0[0]             = MIXV(kma, kmb);
        dst0[(BH_ / 8) * 1] = MIXV(vma, vmb);   // slot stride = BH_/8 uint4
        dst0[(BH_ / 8) * 2] = MIXV(rma, rmb);
        #undef MIXV
    }
}

// ============================================================================
// WKV: warp-per-frag; reads k/v/r (g_lin normal) + states, writes aa/bb/p2
// (normal, outputs) and g (fragment-major slot 3).
// ============================================================================
__device__ __forceinline__ void wkv_comp(float k, float v, float rl,
                                         float A, float Bv, float P,
                                         float tfv, float tdv,
                                         float& aa, float& bb, float& p2o, float& g)
{
    float r = 1.0f / (1.0f + expf(-rl));
    float w = k + tfv;
    float p = fmaxf(P, w);
    float e1 = expf(P - p), e2 = expf(w - p);
    float wkv = (e1 * A + e2 * v) / (e1 * Bv + e2);
    float w2 = P + tdv;
    p2o = fmaxf(w2, k);
    float ea = expf(w2 - p2o), eb = expf(k - p2o);
    aa = ea * A + eb * v;
    bb = ea * Bv + eb;
    g = r * wkv;
}

__global__ void wkv_kernel(const float* __restrict__ sa, const float* __restrict__ sb,
                           const float* __restrict__ sp, const float* __restrict__ td,
                           const float* __restrict__ tf, float* __restrict__ out,
                           int nslots)
{
    const int f = (int)blockIdx.x * 8 + (threadIdx.x >> 5);
    const int lane = threadIdx.x & 31;
    const int row0 = (f >> 8) * 16 + (lane >> 2);
    const int col0 = (f & 255) * 16 + ((lane & 3) << 1);

    const size_t p00 = (size_t)row0 * HDIM + col0;
    const size_t p10 = p00 + 8 * HDIM;
    const size_t P_[4] = {p00, p10, p00 + 8, p10 + 8};

    int h = col0 & (HDIM - 1);
    float2 tfa = *(const float2*)(tf + h), tfb = *(const float2*)(tf + h + 8);
    float2 tda = *(const float2*)(td + h), tdb = *(const float2*)(td + h + 8);
    float tfv[4][2] = {{tfa.x, tfa.y}, {tfa.x, tfa.y}, {tfb.x, tfb.y}, {tfb.x, tfb.y}};
    float tdv[4][2] = {{tda.x, tda.y}, {tda.x, tda.y}, {tdb.x, tdb.y}, {tdb.x, tdb.y}};

    float gg[8];
    #pragma unroll
    for (int q = 0; q < 4; q++) {
        size_t p = P_[q];
        float2 k2 = *(const float2*)(g_lin + p);
        float2 v2 = *(const float2*)(g_lin + BH_ + p);
        float2 r2 = *(const float2*)(g_lin + 2 * BH_ + p);
        float2 A2 = *(const float2*)(sa + p);
        float2 B2 = *(const float2*)(sb + p);
        float2 Pp = *(const float2*)(sp + p);
        float2 aa2, bb2, p22;
        wkv_comp(k2.x, v2.x, r2.x, A2.x, B2.x, Pp.x, tfv[q][0], tdv[q][0],
                 aa2.x, bb2.x, p22.x, gg[q * 2 + 0]);
        wkv_comp(k2.y, v2.y, r2.y, A2.y, B2.y, Pp.y, tfv[q][1], tdv[q][1],
                 aa2.y, bb2.y, p22.y, gg[q * 2 + 1]);
        if (nslots > 2) *(float2*)(out + 2 * BH_ + p) = aa2;
        if (nslots > 3) *(float2*)(out + 3 * BH_ + p) = bb2;
        if (nslots > 4) *(float2*)(out + 4 * BH_ + p) = p22;
    }
    // g -> slot 3 fragment-major
    uint4* dst = (uint4*)g_act + (BH_ / 8) * 3 + (size_t)f * FRAG_U4 + lane;
    *dst = pack8h(gg[0], gg[1], gg[2], gg[3], gg[4], gg[5], gg[6], gg[7]);
}

// ============================================================================
// Launch
// ============================================================================
extern "C" void kernel_launch(void* const* d_in, const int* in_sizes, int n_in,
                              void* d_out, int out_size)
{
    const float* x  = (const float*)d_in[0];
    const float* sx = (const float*)d_in[1];
    const float* sa = (const float*)d_in[2];
    const float* sb = (const float*)d_in[3];
    const float* sp = (const float*)d_in[4];
    const float* td = (const float*)d_in[5];
    const float* tf = (const float*)d_in[6];
    const float* km = (const float*)d_in[7];
    const float* vm = (const float*)d_in[8];
    const float* rm = (const float*)d_in[9];
    const float* Wk = (const float*)d_in[10];
    const float* Wv = (const float*)d_in[11];
    const float* Wr = (const float*)d_in[12];
    const float* Wo = (const float*)d_in[13];
    float* out = (float*)d_out;
    const int nslots = (int)((size_t)out_size / BH_);

    cudaFuncSetAttribute(hgemm_kernel,
                         cudaFuncAttributeMaxDynamicSharedMemorySize, GSMEM);

    // 1) Fused prep: W^T convert + fragment-major token-shift mix
    prep_kernel<<<WSPLIT_BLOCKS + MIX_BLOCKS, 256>>>(
        Wk, Wv, Wr, Wo, x, sx, km, vm, rm, out + BH_, nslots > 1 ? 1 : 0);

    // 2) k, v, r_linear GEMMs
    hgemm_kernel<<<dim3(HDIM / BN, BDIM / BM, 3), GTHREADS, GSMEM>>>(nullptr, 0);

    // 3) WKV elementwise (g written fragment-major to slot 3)
    wkv_kernel<<<(unsigned)(BH_ / 256 / 8), 256>>>(sa, sb, sp, td, tf, out, nslots);

    // 4) out = g @ output_weight
    hgemm_kernel<<<dim3(HDIM / BN, BDIM / BM, 1), GTHREADS, GSMEM>>>(out, 1);
}

// round 12
// speedup vs baseline: 1.5248x; 1.5248x over previous
#include <cuda_runtime.h>
#include <cuda_fp16.h>
#include <cstdint>
#include <cstddef>

// ============================================================================
// Problem constants
// ============================================================================
#define HDIM 4096
#define BDIM 4096
static constexpr size_t BH_ = (size_t)HDIM * (size_t)BDIM;   // 16777216

// ============================================================================
// Device scratch.
//   g_act slots: 0=xk 1=xv 2=xr 3=g(r*wkv)     (fp16, [B,H] K-major)
//   g_wt  slots: 0=Wk^T 1=Wv^T 2=Wr^T 3=Wo^T   (fp16, [N,K] K-major)
//   g_lin slots: 0=k 1=v 2=r_linear            (fp32 [B,H])
//   g_wkv: wkv intermediate (fp32 [B,H])
// ============================================================================
__device__ __align__(128) __half g_act[4 * BH_];
__device__ __align__(128) __half g_wt[4 * BH_];
__device__ __align__(128) float  g_lin[3 * BH_];
__device__ __align__(128) float  g_wkv[BH_];

__device__ __forceinline__ uint32_t smem_u32(const void* p) {
    uint32_t a;
    asm("{ .reg .u64 t; cvta.to.shared.u64 t, %1; cvt.u32.u64 %0, t; }"
        : "=r"(a) : "l"(p));
    return a;
}

#define SWZ(o) ((o) ^ (((o) >> 3) & 0x70))

#define CP_ASYNC16(sa, ga)                                                     \
    asm volatile("cp.async.cg.shared.global [%0], [%1], 16;"                   \
                 :: "r"(sa), "l"(ga))

#define MBAR_INIT(addr, cnt)                                                   \
    asm volatile("mbarrier.init.shared.b64 [%0], %1;"                          \
                 :: "r"(addr), "r"(cnt) : "memory")
#define MBAR_ARRIVE(addr)                                                      \
    asm volatile("mbarrier.arrive.shared.b64 _, [%0];"                         \
                 :: "r"(addr) : "memory")
#define CPASYNC_MBAR_ARRIVE(addr)                                              \
    asm volatile("cp.async.mbarrier.arrive.noinc.shared.b64 [%0];"             \
                 :: "r"(addr) : "memory")

#define MBAR_WAIT(addr, ph) do {                                               \
    uint32_t _m = (uint32_t)(addr), _p = (uint32_t)(ph), _d;                   \
    asm volatile(                                                              \
        "{\n\t.reg .pred p;\n\t"                                               \
        "mbarrier.try_wait.parity.acquire.cta.shared::cta.b64 p, [%1], %2;\n\t"\
        "selp.b32 %0, 1, 0, p;\n\t}"                                           \
        : "=r"(_d) : "r"(_m), "r"(_p) : "memory");                             \
    if (!_d) {                                                                 \
        asm volatile(                                                          \
            "{\n\t.reg .pred P1;\n\t"                                          \
            "WL%=:\n\t"                                                        \
            "mbarrier.try_wait.parity.acquire.cta.shared::cta.b64 P1, [%0], %1, 0x989680;\n\t" \
            "@P1 bra.uni WD%=;\n\t"                                            \
            "bra.uni WL%=;\n\t"                                                \
            "WD%=:\n\t}"                                                       \
            :: "r"(_m), "r"(_p) : "memory");                                   \
    }                                                                          \
} while (0)

#define LDSM_X4(r0, r1, r2, r3, addr)                                          \
    asm volatile("ldmatrix.sync.aligned.m8n8.x4.shared.b16 {%0,%1,%2,%3}, [%4];" \
                 : "=r"(r0), "=r"(r1), "=r"(r2), "=r"(r3) : "r"(addr))

#define MMA16816(c, a, b0, b1)                                                 \
    asm volatile("mma.sync.aligned.m16n8k16.row.col.f32.f16.f16.f32 "          \
                 "{%0,%1,%2,%3}, {%4,%5,%6,%7}, {%8,%9}, {%0,%1,%2,%3};"       \
                 : "+f"((c)[0]), "+f"((c)[1]), "+f"((c)[2]), "+f"((c)[3])      \
                 : "r"((a)[0]), "r"((a)[1]), "r"((a)[2]), "r"((a)[3]),         \
                   "r"(b0), "r"(b1))

// ============================================================================
// GEMM tile (r7 mainloop, r9-verified device function): C = A @ B^T.
// CTA tile 128x128, BK=64, 3-slot mbarrier ring, 4 warps 64x64, occ 2.
// MODE 0: z = tileid>>10 (k/v/r by tile range), C = g_lin slot z.
// MODE 1: z = 3 (g @ Wo^T), C = Cout.
// ============================================================================
#define BM 128
#define BN 128
#define BK 64
#define GTHREADS 128
#define NKITERS (HDIM / BK)                 // 64
#define STAGE_BYTES ((BM + BN) * 128)       // 32768
#define SM_B_OFF (BM * 128)                 // 16384
#define SM_TILE0 1024
#define GSMEM (SM_TILE0 + 3 * STAGE_BYTES)  // 99328

template <int MODE>
__device__ __forceinline__ void gemm_tile(int tileid, float* __restrict__ Cout,
                                          char* smem, int tid)
{
    const uint32_t sb = smem_u32(smem);
    const int wid = tid >> 5;
    const int lane = tid & 31;

    int z, r;
    if (MODE == 0) { z = tileid >> 10; r = tileid & 1023; }
    else           { z = 3;            r = tileid; }
    const int grp = r >> 9, rem = r & 511;
    const int m0 = (rem >> 4) * BM;
    const int n0 = ((grp << 4) + (rem & 15)) * BN;

    const __half* __restrict__ A = g_act + (size_t)z * BH_;
    const __half* __restrict__ Bw = g_wt + (size_t)z * BH_;
    float* __restrict__ C = (MODE == 0) ? (g_lin + (size_t)z * BH_) : Cout;

    if (tid == 0) {
        #pragma unroll
        for (int s = 0; s < 3; s++) {
            MBAR_INIT(sb + s * 16, GTHREADS);
            MBAR_INIT(sb + s * 16 + 8, GTHREADS);
        }
    }
    __syncthreads();

    const int lrow = tid >> 3, lcol = tid & 7;
    const __half* gAb = A + (size_t)(m0 + lrow) * HDIM + lcol * 8;
    const __half* gBb = Bw + (size_t)(n0 + lrow) * HDIM + lcol * 8;
    const uint32_t soff = SWZ((uint32_t)(lrow * 128 + lcol * 16));
    const uint32_t sAb = sb + SM_TILE0 + soff;
    const uint32_t sBb = sb + SM_TILE0 + SM_B_OFF + soff;

    #define LOAD_STAGE(slot, kc) do {                                          \
        uint32_t off = (uint32_t)(slot) * STAGE_BYTES;                         \
        size_t ko = (size_t)(kc) * BK;                                         \
        _Pragma("unroll")                                                      \
        for (int c = 0; c < 8; c++)                                            \
            CP_ASYNC16(sAb + off + c * 2048, gAb + ko + (size_t)c * 16 * HDIM);\
        _Pragma("unroll")                                                      \
        for (int c = 0; c < 8; c++)                                            \
            CP_ASYNC16(sBb + off + c * 2048, gBb + ko + (size_t)c * 16 * HDIM);\
    } while (0)

    const int wm = (wid & 1) * 64;
    const int wn = (wid >> 1) * 64;
    const uint32_t xorv = (uint32_t)((lane & 7) << 4);
    const uint32_t bcol0 = (uint32_t)((lane >> 4) << 4);
    uint32_t rowAoff[4], rowBoff[4];
    #pragma unroll
    for (int mt = 0; mt < 4; mt++)
        rowAoff[mt] = (uint32_t)(SM_TILE0 + (wm + (lane & 15) + mt * 16) * 128);
    #pragma unroll
    for (int nt2 = 0; nt2 < 4; nt2++)
        rowBoff[nt2] = (uint32_t)(SM_TILE0 + SM_B_OFF + (wn + nt2 * 16 + (lane & 15)) * 128);

    float acc[4][8][4];
    #pragma unroll
    for (int mt = 0; mt < 4; mt++)
        #pragma unroll
        for (int nt = 0; nt < 8; nt++)
            #pragma unroll
            for (int e = 0; e < 4; e++) acc[mt][nt][e] = 0.0f;

    uint32_t af[2][4][4], bf[2][4][4];
    #define LOADFRAG(buf, sbase_, ks_) do {                                    \
        const uint32_t bc = ((uint32_t)((ks_) * 32) + bcol0) ^ xorv;           \
        _Pragma("unroll")                                                      \
        for (int mt = 0; mt < 4; mt++)                                         \
            LDSM_X4(af[buf][mt][0], af[buf][mt][1], af[buf][mt][2],            \
                    af[buf][mt][3], (sbase_) + rowAoff[mt] + bc);              \
        _Pragma("unroll")                                                      \
        for (int nt2 = 0; nt2 < 4; nt2++)                                      \
            LDSM_X4(bf[buf][nt2][0], bf[buf][nt2][1], bf[buf][nt2][2],         \
                    bf[buf][nt2][3], (sbase_) + rowBoff[nt2] + bc);            \
    } while (0)

    LOAD_STAGE(0, 0);
    CPASYNC_MBAR_ARRIVE(sb + 0 * 16);
    LOAD_STAGE(1, 1);
    CPASYNC_MBAR_ARRIVE(sb + 1 * 16);

    for (int kc = 0; kc < NKITERS; kc++) {
        const int s = kc - (kc / 3) * 3;
        const int t = kc + 2;
        if (t < NKITERS) {
            const int s2 = t - (t / 3) * 3;
            if (t >= 3)
                MBAR_WAIT(sb + s2 * 16 + 8, ((t - 3) / 3) & 1);
            LOAD_STAGE(s2, t);
            CPASYNC_MBAR_ARRIVE(sb + s2 * 16);
        }
        MBAR_WAIT(sb + s * 16, (kc / 3) & 1);

        const uint32_t sbase = sb + (uint32_t)s * STAGE_BYTES;
        LOADFRAG(0, sbase, 0);
        #pragma unroll
        for (int ks = 0; ks < 4; ks++) {
            const int cur = ks & 1;
            if (ks < 3) LOADFRAG(cur ^ 1, sbase, ks + 1);
            #pragma unroll
            for (int mt = 0; mt < 4; mt++) {
                #pragma unroll
                for (int nt = 0; nt < 8; nt++) {
                    uint32_t b0 = (nt & 1) ? bf[cur][nt >> 1][1] : bf[cur][nt >> 1][0];
                    uint32_t b1 = (nt & 1) ? bf[cur][nt >> 1][3] : bf[cur][nt >> 1][2];
                    MMA16816(acc[mt][nt], af[cur][mt], b0, b1);
                }
            }
        }
        MBAR_ARRIVE(sb + s * 16 + 8);
    }

    const int gr = lane >> 2;
    const int gc = (lane & 3) * 2;
    #pragma unroll
    for (int mt = 0; mt < 4; mt++) {
        #pragma unroll
        for (int nt = 0; nt < 8; nt++) {
            int row = m0 + wm + mt * 16 + gr;
            int col = n0 + wn + nt * 8 + gc;
            float2 v0 = make_float2(acc[mt][nt][0], acc[mt][nt][1]);
            float2 v1 = make_float2(acc[mt][nt][2], acc[mt][nt][3]);
            *(float2*)(C + (size_t)row * HDIM + col) = v0;
            *(float2*)(C + (size_t)(row + 8) * HDIM + col) = v1;
        }
    }
    #undef LOAD_STAGE
    #undef LOADFRAG
}

// ============================================================================
// Work units (all 128-thread blocks)
// ============================================================================
__device__ __forceinline__ void half_store4(int slot, size_t i,
                                            float a0, float a1, float a2, float a3)
{
    union { __half h[4]; uint2 u; } u;
    u.h[0] = __float2half_rn(a0);
    u.h[1] = __float2half_rn(a1);
    u.h[2] = __float2half_rn(a2);
    u.h[3] = __float2half_rn(a3);
    ((uint2*)g_act)[(size_t)slot * (BH_ / 4) + i] = u.u;
}

// mix unit: block b covers 256 float4 (2 iters x 128 threads)
__device__ __forceinline__ void do_mix(int b, int tid,
    const float4* __restrict__ x, const float4* __restrict__ sx,
    const float* __restrict__ km, const float* __restrict__ vm,
    const float* __restrict__ rm, float4* __restrict__ out_x, int do_copy)
{
    #pragma unroll
    for (int it = 0; it < 2; it++) {
        size_t i = (size_t)b * 256 + it * 128 + tid;
        float4 xv = x[i], sv = sx[i];
        int h = (int)((i * 4) & (HDIM - 1));
        float4 kmv = *(const float4*)(km + h);
        float4 vmv = *(const float4*)(vm + h);
        float4 rmv = *(const float4*)(rm + h);
        if (do_copy) out_x[i] = xv;
        half_store4(0, i,
            fmaf(kmv.x, xv.x - sv.x, sv.x), fmaf(kmv.y, xv.y - sv.y, sv.y),
            fmaf(kmv.z, xv.z - sv.z, sv.z), fmaf(kmv.w, xv.w - sv.w, sv.w));
        half_store4(1, i,
            fmaf(vmv.x, xv.x - sv.x, sv.x), fmaf(vmv.y, xv.y - sv.y, sv.y),
            fmaf(vmv.z, xv.z - sv.z, sv.z), fmaf(vmv.w, xv.w - sv.w, sv.w));
        half_store4(2, i,
            fmaf(rmv.x, xv.x - sv.x, sv.x), fmaf(rmv.y, xv.y - sv.y, sv.y),
            fmaf(rmv.z, xv.z - sv.z, sv.z), fmaf(rmv.w, xv.w - sv.w, sv.w));
    }
}

// weight-transpose strip: 32-wide n-strip x 512-deep k (16 tiles of 32x32).
// idx in [0,1024): nstrip = idx & 127, kgrp = idx >> 7.
__device__ __forceinline__ void do_wtstrip(int idx, int z, int tid,
                                           const float* __restrict__ W,
                                           float* tile /* smem 32*33 floats */)
{
    const int n0 = (idx & 127) * 32;
    const int kbase = (idx >> 7) * 512;
    const int row = tid >> 2, c0 = (tid & 3) * 8;   // load role
    const int j = tid >> 2, u = tid & 3;            // store role

    for (int kt = 0; kt < 16; kt++) {
        const int k0t = kbase + kt * 32;
        float4 a = *(const float4*)&W[(size_t)(k0t + row) * HDIM + n0 + c0];
        float4 b = *(const float4*)&W[(size_t)(k0t + row) * HDIM + n0 + c0 + 4];
        tile[row * 33 + c0 + 0] = a.x; tile[row * 33 + c0 + 1] = a.y;
        tile[row * 33 + c0 + 2] = a.z; tile[row * 33 + c0 + 3] = a.w;
        tile[row * 33 + c0 + 4] = b.x; tile[row * 33 + c0 + 5] = b.y;
        tile[row * 33 + c0 + 6] = b.z; tile[row * 33 + c0 + 7] = b.w;
        __syncthreads();
        union { __half h[8]; uint4 q; } o;
        #pragma unroll
        for (int e = 0; e < 8; e++)
            o.h[e] = __float2half_rn(tile[(u * 8 + e) * 33 + j]);
        *(uint4*)&g_wt[(size_t)z * BH_ + (size_t)(n0 + j) * HDIM + k0t + u * 8] = o.q;
        __syncthreads();
    }
}

// wkv_a: aa/bb/p2 + wkv intermediate — needs only k,v (NOT r).
// block w covers 4096 float4 (32 iters x 128 threads)
__device__ __forceinline__ void do_wkva(int w, int tid,
    const float4* __restrict__ sa, const float4* __restrict__ sb,
    const float4* __restrict__ sp, const float* __restrict__ td,
    const float* __restrict__ tf, float* __restrict__ out, int nslots)
{
    const float4* lin = (const float4*)g_lin;
    for (int it = 0; it < 32; it++) {
        size_t i = (size_t)w * 4096 + it * 128 + tid;
        int h = (int)((i * 4) & (HDIM - 1));
        float4 k4 = lin[i];
        float4 v4 = lin[BH_ / 4 + i];
        float4 sa4 = sa[i], sb4 = sb[i], sp4 = sp[i];
        float4 tf4 = *(const float4*)(tf + h);
        float4 td4 = *(const float4*)(td + h);

        float4 aa4, bb4, p24, wk4;
        #define WKVA(c)                                                        \
        do {                                                                   \
            float w_ = k4.c + tf4.c;                                           \
            float p_ = fmaxf(sp4.c, w_);                                       \
            float e1 = expf(sp4.c - p_), e2 = expf(w_ - p_);                   \
            wk4.c = (e1 * sa4.c + e2 * v4.c) / (e1 * sb4.c + e2);              \
            float w2 = sp4.c + td4.c;                                          \
            p24.c = fmaxf(w2, k4.c);                                           \
            float ea = expf(w2 - p24.c), eb = expf(k4.c - p24.c);              \
            aa4.c = ea * sa4.c + eb * v4.c;                                    \
            bb4.c = ea * sb4.c + eb;                                           \
        } while (0)
        WKVA(x); WKVA(y); WKVA(z); WKVA(w);
        #undef WKVA

        if (nslots > 2) ((float4*)(out + 2 * BH_))[i] = aa4;
        if (nslots > 3) ((float4*)(out + 3 * BH_))[i] = bb4;
        if (nslots > 4) ((float4*)(out + 4 * BH_))[i] = p24;
        ((float4*)g_wkv)[i] = wk4;
    }
}

// ============================================================================
// Launch-level kernels
// ============================================================================

// L1: mix (16384 blocks) + Wk,Wv transpose strips (2048 blocks)
__global__ void __launch_bounds__(128)
prep1_kernel(const float* __restrict__ Wk, const float* __restrict__ Wv,
             const float4* __restrict__ x, const float4* __restrict__ sx,
             const float* __restrict__ km, const float* __restrict__ vm,
             const float* __restrict__ rm, float4* __restrict__ out_x,
             int do_copy)
{
    extern __shared__ char smem[];
    int b = (int)blockIdx.x;
    if (b < 16384) {
        do_mix(b, threadIdx.x, x, sx, km, vm, rm, out_x, do_copy);
    } else {
        int t2 = b - 16384;
        int z = t2 >> 10;
        do_wtstrip(t2 & 1023, z, threadIdx.x, z ? Wv : Wk, (float*)smem);
    }
}

// L2: k,v GEMMs (2048) + Wr,Wo transpose strips (2048, backfill tail)
__global__ void __launch_bounds__(GTHREADS, 2)
kv_kernel(const float* __restrict__ Wr, const float* __restrict__ Wo)
{
    extern __shared__ char smem[];
    int b = (int)blockIdx.x;
    if (b < 2048) {
        gemm_tile<0>(b, nullptr, smem, threadIdx.x);
    } else {
        int t2 = b - 2048;
        int z = 2 + (t2 >> 10);
        do_wtstrip(t2 & 1023, z, threadIdx.x, (z == 2) ? Wr : Wo, (float*)smem);
    }
}

// L3: r GEMM (1024) + wkv_a (1024, backfill tail)
__global__ void __launch_bounds__(GTHREADS, 2)
r_kernel(const float4* __restrict__ sa, const float4* __restrict__ sb,
         const float4* __restrict__ sp, const float* __restrict__ td,
         const float* __restrict__ tf, float* __restrict__ out, int nslots)
{
    extern __shared__ char smem[];
    int b = (int)blockIdx.x;
    if (b < 1024) {
        gemm_tile<0>(2048 + b, nullptr, smem, threadIdx.x);
    } else {
        do_wkva(b - 1024, threadIdx.x, sa, sb, sp, td, tf, out, nslots);
    }
}

// L4: g = sigmoid(r) * wkv  (fp16 to act slot 3)
__global__ void __launch_bounds__(256)
wkvb_kernel()
{
    size_t i = (size_t)blockIdx.x * 256 + threadIdx.x;   // over BH/4
    const float4* lin = (const float4*)g_lin;
    float4 r4 = lin[2 * (BH_ / 4) + i];
    float4 w4 = ((const float4*)g_wkv)[i];
    float g0 = w4.x / (1.0f + expf(-r4.x));
    float g1 = w4.y / (1.0f + expf(-r4.y));
    float g2 = w4.z / (1.0f + expf(-r4.z));
    float g3 = w4.w / (1.0f + expf(-r4.w));
    half_store4(3, i, g0, g1, g2, g3);
}

// L5: out = g @ Wo^T
__global__ void __launch_bounds__(GTHREADS, 2)
out_kernel(float* __restrict__ out)
{
    extern __shared__ char smem[];
    gemm_tile<1>((int)blockIdx.x, out, smem, threadIdx.x);
}

// ============================================================================
// Launch
// ============================================================================
extern "C" void kernel_launch(void* const* d_in, const int* in_sizes, int n_in,
                              void* d_out, int out_size)
{
    const float* x  = (const float*)d_in[0];
    const float* sx = (const float*)d_in[1];
    const float* sa = (const float*)d_in[2];
    const float* sb = (const float*)d_in[3];
    const float* sp = (const float*)d_in[4];
    const float* td = (const float*)d_in[5];
    const float* tf = (const float*)d_in[6];
    const float* km = (const float*)d_in[7];
    const float* vm = (const float*)d_in[8];
    const float* rm = (const float*)d_in[9];
    const float* Wk = (const float*)d_in[10];
    const float* Wv = (const float*)d_in[11];
    const float* Wr = (const float*)d_in[12];
    const float* Wo = (const float*)d_in[13];
    float* out = (float*)d_out;
    const int nslots = (int)((size_t)out_size / BH_);

    cudaFuncSetAttribute(kv_kernel,
                         cudaFuncAttributeMaxDynamicSharedMemorySize, GSMEM);
    cudaFuncSetAttribute(r_kernel,
                         cudaFuncAttributeMaxDynamicSharedMemorySize, GSMEM);
    cudaFuncSetAttribute(out_kernel,
                         cudaFuncAttributeMaxDynamicSharedMemorySize, GSMEM);

    // L1: mix + Wk,Wv transpose
    prep1_kernel<<<16384 + 2048, 128, 32 * 33 * 4>>>(
        Wk, Wv, (const float4*)x, (const float4*)sx, km, vm, rm,
        (float4*)(out + BH_), nslots > 1 ? 1 : 0);

    // L2: k,v GEMMs + Wr,Wo transpose (tail backfill)
    kv_kernel<<<2048 + 2048, GTHREADS, GSMEM>>>(Wr, Wo);

    // L3: r GEMM + wkv_a (aa/bb/p2 + wkv; tail backfill)
    r_kernel<<<1024 + 1024, GTHREADS, GSMEM>>>(
        (const float4*)sa, (const float4*)sb, (const float4*)sp, td, tf,
        out, nslots);

    // L4: g = sigmoid(r) * wkv
    wkvb_kernel<<<(unsigned)(BH_ / 4 / 256), 256>>>();

    // L5: out = g @ Wo^T
    out_kernel<<<1024, GTHREADS, GSMEM>>>(out);
}

// round 13
// speedup vs baseline: 1.5422x; 1.0115x over previous
#include <cuda_runtime.h>
#include <cuda_fp16.h>
#include <cstdint>
#include <cstddef>

// ============================================================================
// Problem constants
// ============================================================================
#define HDIM 4096
#define BDIM 4096
static constexpr size_t BH_ = (size_t)HDIM * (size_t)BDIM;   // 16777216

// ============================================================================
// Device scratch.
//   g_act slots: 0=xk 1=xv 2=xr 3=g(r*wkv)     (fp16, [B,H] K-major)
//   g_wt  slots: 0=Wk^T 1=Wv^T 2=Wr^T 3=Wo^T   (fp16, [N,K] K-major)
//   g_lin slots: 0=k 1=v 2=r_linear            (fp32 [B,H])
//   g_wkv: wkv intermediate (fp32 [B,H])
// ============================================================================
__device__ __align__(128) __half g_act[4 * BH_];
__device__ __align__(128) __half g_wt[4 * BH_];
__device__ __align__(128) float  g_lin[3 * BH_];
__device__ __align__(128) float  g_wkv[BH_];

__device__ __forceinline__ uint32_t smem_u32(const void* p) {
    uint32_t a;
    asm("{ .reg .u64 t; cvta.to.shared.u64 t, %1; cvt.u32.u64 %0, t; }"
        : "=r"(a) : "l"(p));
    return a;
}

#define SWZ(o) ((o) ^ (((o) >> 3) & 0x70))

#define CP_ASYNC16(sa, ga)                                                     \
    asm volatile("cp.async.cg.shared.global [%0], [%1], 16;"                   \
                 :: "r"(sa), "l"(ga))

#define MBAR_INIT(addr, cnt)                                                   \
    asm volatile("mbarrier.init.shared.b64 [%0], %1;"                          \
                 :: "r"(addr), "r"(cnt) : "memory")
#define MBAR_ARRIVE(addr)                                                      \
    asm volatile("mbarrier.arrive.shared.b64 _, [%0];"                         \
                 :: "r"(addr) : "memory")
#define CPASYNC_MBAR_ARRIVE(addr)                                              \
    asm volatile("cp.async.mbarrier.arrive.noinc.shared.b64 [%0];"             \
                 :: "r"(addr) : "memory")

#define MBAR_WAIT(addr, ph) do {                                               \
    uint32_t _m = (uint32_t)(addr), _p = (uint32_t)(ph), _d;                   \
    asm volatile(                                                              \
        "{\n\t.reg .pred p;\n\t"                                               \
        "mbarrier.try_wait.parity.acquire.cta.shared::cta.b64 p, [%1], %2;\n\t"\
        "selp.b32 %0, 1, 0, p;\n\t}"                                           \
        : "=r"(_d) : "r"(_m), "r"(_p) : "memory");                             \
    if (!_d) {                                                                 \
        asm volatile(                                                          \
            "{\n\t.reg .pred P1;\n\t"                                          \
            "WL%=:\n\t"                                                        \
            "mbarrier.try_wait.parity.acquire.cta.shared::cta.b64 P1, [%0], %1, 0x989680;\n\t" \
            "@P1 bra.uni WD%=;\n\t"                                            \
            "bra.uni WL%=;\n\t"                                                \
            "WD%=:\n\t}"                                                       \
            :: "r"(_m), "r"(_p) : "memory");                                   \
    }                                                                          \
} while (0)

#define LDSM_X4(r0, r1, r2, r3, addr)                                          \
    asm volatile("ldmatrix.sync.aligned.m8n8.x4.shared.b16 {%0,%1,%2,%3}, [%4];" \
                 : "=r"(r0), "=r"(r1), "=r"(r2), "=r"(r3) : "r"(addr))

#define MMA16816(c, a, b0, b1)                                                 \
    asm volatile("mma.sync.aligned.m16n8k16.row.col.f32.f16.f16.f32 "          \
                 "{%0,%1,%2,%3}, {%4,%5,%6,%7}, {%8,%9}, {%0,%1,%2,%3};"       \
                 : "+f"((c)[0]), "+f"((c)[1]), "+f"((c)[2]), "+f"((c)[3])      \
                 : "r"((a)[0]), "r"((a)[1]), "r"((a)[2]), "r"((a)[3]),         \
                   "r"(b0), "r"(b1))

// ============================================================================
// GEMM tile (r7 mainloop, verified): C = A @ B^T.
// CTA tile 128x128, BK=64, 3-slot mbarrier ring, 4 warps 64x64, occ 2.
// ============================================================================
#define BM 128
#define BN 128
#define BK 64
#define GTHREADS 128
#define NKITERS (HDIM / BK)                 // 64
#define STAGE_BYTES ((BM + BN) * 128)       // 32768
#define SM_B_OFF (BM * 128)                 // 16384
#define SM_TILE0 1024
#define GSMEM (SM_TILE0 + 3 * STAGE_BYTES)  // 99328

template <int MODE>
__device__ __forceinline__ void gemm_tile(int tileid, float* __restrict__ Cout,
                                          char* smem, int tid)
{
    const uint32_t sb = smem_u32(smem);
    const int wid = tid >> 5;
    const int lane = tid & 31;

    int z, r;
    if (MODE == 0) { z = tileid >> 10; r = tileid & 1023; }
    else           { z = 3;            r = tileid; }
    const int grp = r >> 9, rem = r & 511;
    const int m0 = (rem >> 4) * BM;
    const int n0 = ((grp << 4) + (rem & 15)) * BN;

    const __half* __restrict__ A = g_act + (size_t)z * BH_;
    const __half* __restrict__ Bw = g_wt + (size_t)z * BH_;
    float* __restrict__ C = (MODE == 0) ? (g_lin + (size_t)z * BH_) : Cout;

    if (tid == 0) {
        #pragma unroll
        for (int s = 0; s < 3; s++) {
            MBAR_INIT(sb + s * 16, GTHREADS);
            MBAR_INIT(sb + s * 16 + 8, GTHREADS);
        }
    }
    __syncthreads();

    const int lrow = tid >> 3, lcol = tid & 7;
    const __half* gAb = A + (size_t)(m0 + lrow) * HDIM + lcol * 8;
    const __half* gBb = Bw + (size_t)(n0 + lrow) * HDIM + lcol * 8;
    const uint32_t soff = SWZ((uint32_t)(lrow * 128 + lcol * 16));
    const uint32_t sAb = sb + SM_TILE0 + soff;
    const uint32_t sBb = sb + SM_TILE0 + SM_B_OFF + soff;

    #define LOAD_STAGE(slot, kc) do {                                          \
        uint32_t off = (uint32_t)(slot) * STAGE_BYTES;                         \
        size_t ko = (size_t)(kc) * BK;                                         \
        _Pragma("unroll")                                                      \
        for (int c = 0; c < 8; c++)                                            \
            CP_ASYNC16(sAb + off + c * 2048, gAb + ko + (size_t)c * 16 * HDIM);\
        _Pragma("unroll")                                                      \
        for (int c = 0; c < 8; c++)                                            \
            CP_ASYNC16(sBb + off + c * 2048, gBb + ko + (size_t)c * 16 * HDIM);\
    } while (0)

    const int wm = (wid & 1) * 64;
    const int wn = (wid >> 1) * 64;
    const uint32_t xorv = (uint32_t)((lane & 7) << 4);
    const uint32_t bcol0 = (uint32_t)((lane >> 4) << 4);
    uint32_t rowAoff[4], rowBoff[4];
    #pragma unroll
    for (int mt = 0; mt < 4; mt++)
        rowAoff[mt] = (uint32_t)(SM_TILE0 + (wm + (lane & 15) + mt * 16) * 128);
    #pragma unroll
    for (int nt2 = 0; nt2 < 4; nt2++)
        rowBoff[nt2] = (uint32_t)(SM_TILE0 + SM_B_OFF + (wn + nt2 * 16 + (lane & 15)) * 128);

    float acc[4][8][4];
    #pragma unroll
    for (int mt = 0; mt < 4; mt++)
        #pragma unroll
        for (int nt = 0; nt < 8; nt++)
            #pragma unroll
            for (int e = 0; e < 4; e++) acc[mt][nt][e] = 0.0f;

    uint32_t af[2][4][4], bf[2][4][4];
    #define LOADFRAG(buf, sbase_, ks_) do {                                    \
        const uint32_t bc = ((uint32_t)((ks_) * 32) + bcol0) ^ xorv;           \
        _Pragma("unroll")                                                      \
        for (int mt = 0; mt < 4; mt++)                                         \
            LDSM_X4(af[buf][mt][0], af[buf][mt][1], af[buf][mt][2],            \
                    af[buf][mt][3], (sbase_) + rowAoff[mt] + bc);              \
        _Pragma("unroll")                                                      \
        for (int nt2 = 0; nt2 < 4; nt2++)                                      \
            LDSM_X4(bf[buf][nt2][0], bf[buf][nt2][1], bf[buf][nt2][2],         \
                    bf[buf][nt2][3], (sbase_) + rowBoff[nt2] + bc);            \
    } while (0)

    LOAD_STAGE(0, 0);
    CPASYNC_MBAR_ARRIVE(sb + 0 * 16);
    LOAD_STAGE(1, 1);
    CPASYNC_MBAR_ARRIVE(sb + 1 * 16);

    for (int kc = 0; kc < NKITERS; kc++) {
        const int s = kc - (kc / 3) * 3;
        const int t = kc + 2;
        if (t < NKITERS) {
            const int s2 = t - (t / 3) * 3;
            if (t >= 3)
                MBAR_WAIT(sb + s2 * 16 + 8, ((t - 3) / 3) & 1);
            LOAD_STAGE(s2, t);
            CPASYNC_MBAR_ARRIVE(sb + s2 * 16);
        }
        MBAR_WAIT(sb + s * 16, (kc / 3) & 1);

        const uint32_t sbase = sb + (uint32_t)s * STAGE_BYTES;
        LOADFRAG(0, sbase, 0);
        #pragma unroll
        for (int ks = 0; ks < 4; ks++) {
            const int cur = ks & 1;
            if (ks < 3) LOADFRAG(cur ^ 1, sbase, ks + 1);
            #pragma unroll
            for (int mt = 0; mt < 4; mt++) {
                #pragma unroll
                for (int nt = 0; nt < 8; nt++) {
                    uint32_t b0 = (nt & 1) ? bf[cur][nt >> 1][1] : bf[cur][nt >> 1][0];
                    uint32_t b1 = (nt & 1) ? bf[cur][nt >> 1][3] : bf[cur][nt >> 1][2];
                    MMA16816(acc[mt][nt], af[cur][mt], b0, b1);
                }
            }
        }
        MBAR_ARRIVE(sb + s * 16 + 8);
    }

    const int gr = lane >> 2;
    const int gc = (lane & 3) * 2;
    #pragma unroll
    for (int mt = 0; mt < 4; mt++) {
        #pragma unroll
        for (int nt = 0; nt < 8; nt++) {
            int row = m0 + wm + mt * 16 + gr;
            int col = n0 + wn + nt * 8 + gc;
            float2 v0 = make_float2(acc[mt][nt][0], acc[mt][nt][1]);
            float2 v1 = make_float2(acc[mt][nt][2], acc[mt][nt][3]);
            *(float2*)(C + (size_t)row * HDIM + col) = v0;
            *(float2*)(C + (size_t)(row + 8) * HDIM + col) = v1;
        }
    }
    #undef LOAD_STAGE
    #undef LOADFRAG
}

__global__ void __launch_bounds__(GTHREADS, 2)
kv_gemm_kernel() {
    extern __shared__ char smem[];
    gemm_tile<0>((int)blockIdx.x, nullptr, smem, threadIdx.x);          // z 0,1
}
__global__ void __launch_bounds__(GTHREADS, 2)
r_gemm_kernel() {
    extern __shared__ char smem[];
    gemm_tile<0>(2048 + (int)blockIdx.x, nullptr, smem, threadIdx.x);   // z 2
}
__global__ void __launch_bounds__(GTHREADS, 2)
out_gemm_kernel(float* __restrict__ out) {
    extern __shared__ char smem[];
    gemm_tile<1>((int)blockIdx.x, out, smem, threadIdx.x);
}

// ============================================================================
// Prep kernels (r7-style 256-thread blocks)
// ============================================================================
__device__ __forceinline__ void half_store4(int slot, size_t i,
                                            float a0, float a1, float a2, float a3)
{
    union { __half h[4]; uint2 u; } u;
    u.h[0] = __float2half_rn(a0);
    u.h[1] = __float2half_rn(a1);
    u.h[2] = __float2half_rn(a2);
    u.h[3] = __float2half_rn(a3);
    ((uint2*)g_act)[(size_t)slot * (BH_ / 4) + i] = u.u;
}

__device__ __forceinline__ void wsplit_tile(int z, int r, int tidx,
                                            const float* __restrict__ W,
                                            float (*tile)[33])
{
    const int n0 = (r & 127) * 32;
    const int k0 = (r >> 7) * 32;
    const int tx = tidx & 31, ty = tidx >> 5;   // 32 x 8

    #pragma unroll
    for (int i = 0; i < 4; i++)
        tile[ty + 8 * i][tx] = W[(size_t)(k0 + ty + 8 * i) * HDIM + (n0 + tx)];
    __syncthreads();

    const size_t base = (size_t)z * BH_;
    #pragma unroll
    for (int i = 0; i < 4; i++) {
        float v = tile[tx][ty + 8 * i];
        g_wt[base + (size_t)(n0 + ty + 8 * i) * HDIM + (k0 + tx)] = __float2half_rn(v);
    }
}

// prep_a: Wk,Wv transpose (32768 blocks) + mix (16384 blocks)
__global__ void prep_a_kernel(const float* __restrict__ Wk, const float* __restrict__ Wv,
                              const float4* __restrict__ x, const float4* __restrict__ sx,
                              const float* __restrict__ km, const float* __restrict__ vm,
                              const float* __restrict__ rm, float4* __restrict__ out_x,
                              int do_copy)
{
    __shared__ float tile[32][33];
    int b = (int)blockIdx.x;
    if (b < 32768) {
        const int z = b >> 14;                  // 0 or 1
        wsplit_tile(z, b & 16383, threadIdx.x, z ? Wv : Wk, tile);
    } else {
        size_t i = (size_t)(b - 32768) * 256 + threadIdx.x;   // over BH/4
        float4 xv = x[i], sv = sx[i];
        int h = (int)((i * 4) & (HDIM - 1));
        float4 kmv = *(const float4*)(km + h);
        float4 vmv = *(const float4*)(vm + h);
        float4 rmv = *(const float4*)(rm + h);
        if (do_copy) out_x[i] = xv;
        half_store4(0, i,
            fmaf(kmv.x, xv.x - sv.x, sv.x), fmaf(kmv.y, xv.y - sv.y, sv.y),
            fmaf(kmv.z, xv.z - sv.z, sv.z), fmaf(kmv.w, xv.w - sv.w, sv.w));
        half_store4(1, i,
            fmaf(vmv.x, xv.x - sv.x, sv.x), fmaf(vmv.y, xv.y - sv.y, sv.y),
            fmaf(vmv.z, xv.z - sv.z, sv.z), fmaf(vmv.w, xv.w - sv.w, sv.w));
        half_store4(2, i,
            fmaf(rmv.x, xv.x - sv.x, sv.x), fmaf(rmv.y, xv.y - sv.y, sv.y),
            fmaf(rmv.z, xv.z - sv.z, sv.z), fmaf(rmv.w, xv.w - sv.w, sv.w));
    }
}

// prep_b: Wr,Wo transpose (32768 blocks) — runs on stream 1 under kv GEMM
__global__ void prep_b_kernel(const float* __restrict__ Wr, const float* __restrict__ Wo)
{
    __shared__ float tile[32][33];
    int b = (int)blockIdx.x;
    const int z = 2 + (b >> 14);                // 2 or 3
    wsplit_tile(z, b & 16383, threadIdx.x, (z == 2) ? Wr : Wo, tile);
}

// ============================================================================
// wkva: aa/bb/p2 + wkv intermediate (needs only k,v) — stream 1 under r GEMM
// ============================================================================
__global__ void wkva_kernel(const float4* __restrict__ sa, const float4* __restrict__ sb,
                            const float4* __restrict__ sp, const float* __restrict__ td,
                            const float* __restrict__ tf, float* __restrict__ out,
                            int nslots)
{
    size_t i = (size_t)blockIdx.x * blockDim.x + threadIdx.x;    // over BH/4
    int h = (int)((i * 4) & (HDIM - 1));
    const float4* lin = (const float4*)g_lin;
    float4 k4 = lin[i];
    float4 v4 = lin[BH_ / 4 + i];
    float4 sa4 = sa[i], sb4 = sb[i], sp4 = sp[i];
    float4 tf4 = *(const float4*)(tf + h);
    float4 td4 = *(const float4*)(td + h);

    float4 aa4, bb4, p24, wk4;
    #define WKVA(c)                                                            \
    do {                                                                       \
        float w_ = k4.c + tf4.c;                                               \
        float p_ = fmaxf(sp4.c, w_);                                           \
        float e1 = expf(sp4.c - p_), e2 = expf(w_ - p_);                       \
        wk4.c = (e1 * sa4.c + e2 * v4.c) / (e1 * sb4.c + e2);                  \
        float w2 = sp4.c + td4.c;                                              \
        p24.c = fmaxf(w2, k4.c);                                               \
        float ea = expf(w2 - p24.c), eb = expf(k4.c - p24.c);                  \
        aa4.c = ea * sa4.c + eb * v4.c;                                        \
        bb4.c = ea * sb4.c + eb;                                               \
    } while (0)
    WKVA(x); WKVA(y); WKVA(z); WKVA(w);
    #undef WKVA

    if (nslots > 2) ((float4*)(out + 2 * BH_))[i] = aa4;
    if (nslots > 3) ((float4*)(out + 3 * BH_))[i] = bb4;
    if (nslots > 4) ((float4*)(out + 4 * BH_))[i] = p24;
    ((float4*)g_wkv)[i] = wk4;
}

// wkvb: g = sigmoid(r) * wkv  (fp16 to act slot 3) — exact r7 math
__global__ void wkvb_kernel()
{
    size_t i = (size_t)blockIdx.x * blockDim.x + threadIdx.x;    // over BH/4
    const float4* lin = (const float4*)g_lin;
    float4 r4 = lin[2 * (BH_ / 4) + i];
    float4 w4 = ((const float4*)g_wkv)[i];
    float r0 = 1.0f / (1.0f + expf(-r4.x));
    float r1 = 1.0f / (1.0f + expf(-r4.y));
    float r2 = 1.0f / (1.0f + expf(-r4.z));
    float r3 = 1.0f / (1.0f + expf(-r4.w));
    half_store4(3, i, r0 * w4.x, r1 * w4.y, r2 * w4.z, r3 * w4.w);
}

// ============================================================================
// Launch: fork-join two-stream schedule (graph-capture-legal pattern)
// ============================================================================
extern "C" void kernel_launch(void* const* d_in, const int* in_sizes, int n_in,
                              void* d_out, int out_size)
{
    const float* x  = (const float*)d_in[0];
    const float* sx = (const float*)d_in[1];
    const float* sa = (const float*)d_in[2];
    const float* sb = (const float*)d_in[3];
    const float* sp = (const float*)d_in[4];
    const float* td = (const float*)d_in[5];
    const float* tf = (const float*)d_in[6];
    const float* km = (const float*)d_in[7];
    const float* vm = (const float*)d_in[8];
    const float* rm = (const float*)d_in[9];
    const float* Wk = (const float*)d_in[10];
    const float* Wv = (const float*)d_in[11];
    const float* Wr = (const float*)d_in[12];
    const float* Wo = (const float*)d_in[13];
    float* out = (float*)d_out;
    const int nslots = (int)((size_t)out_size / BH_);

    static bool inited = false;
    static cudaStream_t s1;
    static cudaEvent_t evF, evK, ev1, ev2;
    if (!inited) {
        cudaStreamCreateWithFlags(&s1, cudaStreamNonBlocking);
        cudaEventCreateWithFlags(&evF, cudaEventDisableTiming);
        cudaEventCreateWithFlags(&evK, cudaEventDisableTiming);
        cudaEventCreateWithFlags(&ev1, cudaEventDisableTiming);
        cudaEventCreateWithFlags(&ev2, cudaEventDisableTiming);
        cudaFuncSetAttribute(kv_gemm_kernel,
                             cudaFuncAttributeMaxDynamicSharedMemorySize, GSMEM);
        cudaFuncSetAttribute(r_gemm_kernel,
                             cudaFuncAttributeMaxDynamicSharedMemorySize, GSMEM);
        cudaFuncSetAttribute(out_gemm_kernel,
                             cudaFuncAttributeMaxDynamicSharedMemorySize, GSMEM);
        inited = true;
    }

    // s0: prep_a (mix + Wk,Wv transpose)
    prep_a_kernel<<<32768 + 16384, 256>>>(
        Wk, Wv, (const float4*)x, (const float4*)sx, km, vm, rm,
        (float4*)(out + BH_), nslots > 1 ? 1 : 0);

    // fork: s1 runs Wr,Wo transpose concurrently with kv GEMM
    cudaEventRecord(evF, 0);
    cudaStreamWaitEvent(s1, evF, 0);
    prep_b_kernel<<<32768, 256, 0, s1>>>(Wr, Wo);
    cudaEventRecord(ev1, s1);

    // s0: k,v GEMMs
    kv_gemm_kernel<<<2048, GTHREADS, GSMEM>>>();

    // fork: s1 runs wkva (needs only k,v) concurrently with r GEMM
    cudaEventRecord(evK, 0);
    cudaStreamWaitEvent(s1, evK, 0);
    wkva_kernel<<<(unsigned)(BH_ / 4 / 256), 256, 0, s1>>>(
        (const float4*)sa, (const float4*)sb, (const float4*)sp, td, tf,
        out, nslots);
    cudaEventRecord(ev2, s1);

    // s0: r GEMM (needs Wr^T from prep_b)
    cudaStreamWaitEvent(0, ev1, 0);
    r_gemm_kernel<<<1024, GTHREADS, GSMEM>>>();

    // join: wkvb needs r + wkv
    cudaStreamWaitEvent(0, ev2, 0);
    wkvb_kernel<<<(unsigned)(BH_ / 4 / 256), 256>>>();

    // s0: out = g @ Wo^T
    out_gemm_kernel<<<1024, GTHREADS, GSMEM>>>(out);
}

// round 14
// speedup vs baseline: 1.5907x; 1.0314x over previous
#include <cuda_runtime.h>
#include <cuda_fp16.h>
#include <cstdint>
#include <cstddef>

// ============================================================================
// Problem constants
// ============================================================================
#define HDIM 4096
#define BDIM 4096
static constexpr size_t BH_ = (size_t)HDIM * (size_t)BDIM;   // 16777216

// ============================================================================
// Device scratch (__device__ globals; allocation is forbidden).
//   g_act slots: 0=xk 1=xv 2=xr 3=g(r*wkv)     (fp16, [B,H] K-major)
//   g_wt  slots: 0=Wk^T 1=Wv^T 2=Wr^T 3=Wo^T   (fp16, [N,K] K-major)
//   g_lin slots: 0=k 1=v 2=r_linear            (fp32 [B,H])
// ============================================================================
__device__ __align__(128) __half g_act[4 * BH_];
__device__ __align__(128) __half g_wt[4 * BH_];
__device__ __align__(128) float  g_lin[3 * BH_];

__device__ __forceinline__ uint32_t smem_u32(const void* p) {
    uint32_t a;
    asm("{ .reg .u64 t; cvta.to.shared.u64 t, %1; cvt.u32.u64 %0, t; }"
        : "=r"(a) : "l"(p));
    return a;
}

#define SWZ(o) ((o) ^ (((o) >> 3) & 0x70))

#define CP_ASYNC16(sa, ga)                                                     \
    asm volatile("cp.async.cg.shared.global [%0], [%1], 16;"                   \
                 :: "r"(sa), "l"(ga))

#define MBAR_INIT(addr, cnt)                                                   \
    asm volatile("mbarrier.init.shared.b64 [%0], %1;"                          \
                 :: "r"(addr), "r"(cnt) : "memory")
#define MBAR_ARRIVE(addr)                                                      \
    asm volatile("mbarrier.arrive.shared.b64 _, [%0];"                         \
                 :: "r"(addr) : "memory")
#define CPASYNC_MBAR_ARRIVE(addr)                                              \
    asm volatile("cp.async.mbarrier.arrive.noinc.shared.b64 [%0];"             \
                 :: "r"(addr) : "memory")

#define MBAR_WAIT(addr, ph) do {                                               \
    uint32_t _m = (uint32_t)(addr), _p = (uint32_t)(ph), _d;                   \
    asm volatile(                                                              \
        "{\n\t.reg .pred p;\n\t"                                               \
        "mbarrier.try_wait.parity.acquire.cta.shared::cta.b64 p, [%1], %2;\n\t"\
        "selp.b32 %0, 1, 0, p;\n\t}"                                           \
        : "=r"(_d) : "r"(_m), "r"(_p) : "memory");                             \
    if (!_d) {                                                                 \
        asm volatile(                                                          \
            "{\n\t.reg .pred P1;\n\t"                                          \
            "WL%=:\n\t"                                                        \
            "mbarrier.try_wait.parity.acquire.cta.shared::cta.b64 P1, [%0], %1, 0x989680;\n\t" \
            "@P1 bra.uni WD%=;\n\t"                                            \
            "bra.uni WL%=;\n\t"                                                \
            "WD%=:\n\t}"                                                       \
            :: "r"(_m), "r"(_p) : "memory");                                   \
    }                                                                          \
} while (0)

#define LDSM_X4(r0, r1, r2, r3, addr)                                          \
    asm volatile("ldmatrix.sync.aligned.m8n8.x4.shared.b16 {%0,%1,%2,%3}, [%4];" \
                 : "=r"(r0), "=r"(r1), "=r"(r2), "=r"(r3) : "r"(addr))

#define MMA16816(c, a, b0, b1)                                                 \
    asm volatile("mma.sync.aligned.m16n8k16.row.col.f32.f16.f16.f32 "          \
                 "{%0,%1,%2,%3}, {%4,%5,%6,%7}, {%8,%9}, {%0,%1,%2,%3};"       \
                 : "+f"((c)[0]), "+f"((c)[1]), "+f"((c)[2]), "+f"((c)[3])      \
                 : "r"((a)[0]), "r"((a)[1]), "r"((a)[2]), "r"((a)[3]),         \
                   "r"(b0), "r"(b1))

// ============================================================================
// HGEMM (r7 pipeline, triple-unrolled k-loop): C[M,N] = A[M,K] @ B^T.
// CTA tile 128x128, BK=64, 3-slot mbarrier ring, 4 warps 64x64, occ 2.
// Unroll by 3 makes every mbarrier slot index and phase parity a
// compile-time constant (no div/mod in the loop; producer/consumer schedule
// identical to r7 — verified chunk-by-chunk for a=0,1,20 and tail kc=63).
// ============================================================================
#define BM 128
#define BN 128
#define BK 64
#define GTHREADS 128
#define NKITERS (HDIM / BK)                 // 64 = 3*21 + 1
#define STAGE_BYTES ((BM + BN) * 128)       // 32768
#define SM_B_OFF (BM * 128)                 // 16384
#define SM_TILE0 1024
#define GSMEM (SM_TILE0 + 3 * STAGE_BYTES)  // 99328

__global__ void __launch_bounds__(GTHREADS, 2)
hgemm_kernel(float* __restrict__ Cout, int mode)
{
    extern __shared__ char smem[];
    const uint32_t sb = smem_u32(smem);
    const int tid = threadIdx.x;
    const int wid = tid >> 5;
    const int lane = tid & 31;

    const int z = (mode == 0) ? (int)blockIdx.z : 3;
    const __half* __restrict__ A = g_act + (size_t)z * BH_;
    const __half* __restrict__ Bw = g_wt + (size_t)z * BH_;
    float* __restrict__ C = (mode == 0) ? (g_lin + (size_t)z * BH_) : Cout;

    // ---- CTA swizzle: 16-wide x-groups (better L2 reuse per wave) ----
    const int bidlin = (int)(blockIdx.x + gridDim.x * blockIdx.y);
    const int per = 16 * (int)gridDim.y;
    const int grp = bidlin / per;
    const int rem = bidlin - grp * per;
    const int m0 = (rem / 16) * BM;
    const int n0 = (grp * 16 + (rem % 16)) * BN;

    // ---- mbarrier init: full[s] at sb+16s, empty[s] at sb+16s+8 ----
    if (tid == 0) {
        #pragma unroll
        for (int s = 0; s < 3; s++) {
            MBAR_INIT(sb + s * 16, GTHREADS);
            MBAR_INIT(sb + s * 16 + 8, GTHREADS);
        }
    }
    __syncthreads();

    // ---- cp.async bases ----
    const int lrow = tid >> 3, lcol = tid & 7;
    const __half* gAb = A + (size_t)(m0 + lrow) * HDIM + lcol * 8;
    const __half* gBb = Bw + (size_t)(n0 + lrow) * HDIM + lcol * 8;
    const uint32_t soff = SWZ((uint32_t)(lrow * 128 + lcol * 16));
    const uint32_t sAb = sb + SM_TILE0 + soff;
    const uint32_t sBb = sb + SM_TILE0 + SM_B_OFF + soff;

    #define LOAD_STAGE(slot, kc) do {                                          \
        uint32_t off = (uint32_t)(slot) * STAGE_BYTES;                         \
        size_t ko = (size_t)(kc) * BK;                                         \
        _Pragma("unroll")                                                      \
        for (int c = 0; c < 8; c++)                                            \
            CP_ASYNC16(sAb + off + c * 2048, gAb + ko + (size_t)c * 16 * HDIM);\
        _Pragma("unroll")                                                      \
        for (int c = 0; c < 8; c++)                                            \
            CP_ASYNC16(sBb + off + c * 2048, gBb + ko + (size_t)c * 16 * HDIM);\
    } while (0)

    // ---- warp tiling: 2x2 warps, each 64x64 ----
    const int wm = (wid & 1) * 64;
    const int wn = (wid >> 1) * 64;
    const uint32_t xorv = (uint32_t)((lane & 7) << 4);
    const uint32_t bcol0 = (uint32_t)((lane >> 4) << 4);
    uint32_t rowAoff[4], rowBoff[4];
    #pragma unroll
    for (int mt = 0; mt < 4; mt++)
        rowAoff[mt] = (uint32_t)(SM_TILE0 + (wm + (lane & 15) + mt * 16) * 128);
    #pragma unroll
    for (int nt2 = 0; nt2 < 4; nt2++)
        rowBoff[nt2] = (uint32_t)(SM_TILE0 + SM_B_OFF + (wn + nt2 * 16 + (lane & 15)) * 128);

    float acc[4][8][4];
    #pragma unroll
    for (int mt = 0; mt < 4; mt++)
        #pragma unroll
        for (int nt = 0; nt < 8; nt++)
            #pragma unroll
            for (int e = 0; e < 4; e++) acc[mt][nt][e] = 0.0f;

    uint32_t af[2][4][4], bf[2][4][4];
    #define LOADFRAG(buf, sbase_, ks_) do {                                    \
        const uint32_t bc = ((uint32_t)((ks_) * 32) + bcol0) ^ xorv;           \
        _Pragma("unroll")                                                      \
        for (int mt = 0; mt < 4; mt++)                                         \
            LDSM_X4(af[buf][mt][0], af[buf][mt][1], af[buf][mt][2],            \
                    af[buf][mt][3], (sbase_) + rowAoff[mt] + bc);              \
        _Pragma("unroll")                                                      \
        for (int nt2 = 0; nt2 < 4; nt2++)                                      \
            LDSM_X4(bf[buf][nt2][0], bf[buf][nt2][1], bf[buf][nt2][2],         \
                    bf[buf][nt2][3], (sbase_) + rowBoff[nt2] + bc);            \
    } while (0)

    // compute one chunk resident in slot SLOT, then release it
    #define COMPUTE_CHUNK(SLOT) do {                                           \
        const uint32_t sbase = sb + (uint32_t)(SLOT) * STAGE_BYTES;            \
        LOADFRAG(0, sbase, 0);                                                 \
        _Pragma("unroll")                                                      \
        for (int ks = 0; ks < 4; ks++) {                                       \
            const int cur = ks & 1;                                            \
            if (ks < 3) LOADFRAG(cur ^ 1, sbase, ks + 1);                      \
            _Pragma("unroll")                                                  \
            for (int mt = 0; mt < 4; mt++) {                                   \
                _Pragma("unroll")                                              \
                for (int nt = 0; nt < 8; nt++) {                               \
                    uint32_t b0 = (nt & 1) ? bf[cur][nt >> 1][1] : bf[cur][nt >> 1][0]; \
                    uint32_t b1 = (nt & 1) ? bf[cur][nt >> 1][3] : bf[cur][nt >> 1][2]; \
                    MMA16816(acc[mt][nt], af[cur][mt], b0, b1);                \
                }                                                              \
            }                                                                  \
        }                                                                      \
        MBAR_ARRIVE(sb + (SLOT) * 16 + 8);                                     \
    } while (0)

    // ---- prologue: chunks 0,1 -> slots 0,1 ----
    LOAD_STAGE(0, 0);
    CPASYNC_MBAR_ARRIVE(sb + 0 * 16);
    LOAD_STAGE(1, 1);
    CPASYNC_MBAR_ARRIVE(sb + 1 * 16);

    // ---- triple-unrolled mainloop: chunks 3a, 3a+1, 3a+2 for a in [0,21) ----
    for (int a = 0; a < 21; a++) {
        const uint32_t ph = (uint32_t)(a & 1);

        // kc = 3a: produce chunk 3a+2 -> slot 2 (empty-wait (a-1)&1, skip a=0)
        if (a >= 1) MBAR_WAIT(sb + 2 * 16 + 8, (uint32_t)((a - 1) & 1));
        LOAD_STAGE(2, 3 * a + 2);
        CPASYNC_MBAR_ARRIVE(sb + 2 * 16);
        MBAR_WAIT(sb + 0 * 16, ph);
        COMPUTE_CHUNK(0);

        // kc = 3a+1: produce chunk 3a+3 -> slot 0 (empty-wait a&1)
        MBAR_WAIT(sb + 0 * 16 + 8, ph);
        LOAD_STAGE(0, 3 * a + 3);
        CPASYNC_MBAR_ARRIVE(sb + 0 * 16);
        MBAR_WAIT(sb + 1 * 16, ph);
        COMPUTE_CHUNK(1);

        // kc = 3a+2: produce chunk 3a+4 -> slot 1 (gated a<20; empty-wait a&1)
        if (a < 20) {
            MBAR_WAIT(sb + 1 * 16 + 8, ph);
            LOAD_STAGE(1, 3 * a + 4);
            CPASYNC_MBAR_ARRIVE(sb + 1 * 16);
        }
        MBAR_WAIT(sb + 2 * 16, ph);
        COMPUTE_CHUNK(2);
    }
    // ---- tail chunk 63: slot 0, phase parity 1 ----
    MBAR_WAIT(sb + 0 * 16, 1u);
    COMPUTE_CHUNK(0);

    // ---- epilogue ----
    const int gr = lane >> 2;
    const int gc = (lane & 3) * 2;
    #pragma unroll
    for (int mt = 0; mt < 4; mt++) {
        #pragma unroll
        for (int nt = 0; nt < 8; nt++) {
            int row = m0 + wm + mt * 16 + gr;
            int col = n0 + wn + nt * 8 + gc;
            float2 v0 = make_float2(acc[mt][nt][0], acc[mt][nt][1]);
            float2 v1 = make_float2(acc[mt][nt][2], acc[mt][nt][3]);
            *(float2*)(C + (size_t)row * HDIM + col) = v0;
            *(float2*)(C + (size_t)(row + 8) * HDIM + col) = v1;
        }
    }
    #undef LOAD_STAGE
    #undef LOADFRAG
    #undef COMPUTE_CHUNK
}

// ============================================================================
// Fused prep kernel: weight transpose+fp16 convert AND token-shift mixing.
// ============================================================================
#define WSPLIT_BLOCKS (4 * (HDIM / 32) * (HDIM / 32))   // 65536
#define MIX_BLOCKS ((int)(BH_ / 4 / 256))               // 16384

__device__ __forceinline__ void half_store4(int slot, size_t i,
                                            float a0, float a1, float a2, float a3)
{
    union { __half h[4]; uint2 u; } u;
    u.h[0] = __float2half_rn(a0);
    u.h[1] = __float2half_rn(a1);
    u.h[2] = __float2half_rn(a2);
    u.h[3] = __float2half_rn(a3);
    ((uint2*)g_act)[(size_t)slot * (BH_ / 4) + i] = u.u;
}

__global__ void prep_kernel(const float* __restrict__ W0, const float* __restrict__ W1,
                            const float* __restrict__ W2, const float* __restrict__ W3,
                            const float4* __restrict__ x, const float4* __restrict__ sx,
                            const float* __restrict__ km, const float* __restrict__ vm,
                            const float* __restrict__ rm, float4* __restrict__ out_x,
                            int do_copy)
{
    __shared__ float tile[32][33];
    int b = (int)blockIdx.x;
    if (b < WSPLIT_BLOCKS) {
        const int z = b >> 14;                   // / (128*128)
        const int r = b & 16383;
        const int n0 = (r & 127) * 32;
        const int k0 = (r >> 7) * 32;
        const float* W = (z == 0) ? W0 : (z == 1) ? W1 : (z == 2) ? W2 : W3;
        const int tx = threadIdx.x & 31, ty = threadIdx.x >> 5;   // 32 x 8

        #pragma unroll
        for (int i = 0; i < 4; i++)
            tile[ty + 8 * i][tx] = W[(size_t)(k0 + ty + 8 * i) * HDIM + (n0 + tx)];
        __syncthreads();

        const size_t base = (size_t)z * BH_;
        #pragma unroll
        for (int i = 0; i < 4; i++) {
            float v = tile[tx][ty + 8 * i];
            g_wt[base + (size_t)(n0 + ty + 8 * i) * HDIM + (k0 + tx)] = __float2half_rn(v);
        }
    } else {
        b -= WSPLIT_BLOCKS;
        size_t i = (size_t)b * 256 + threadIdx.x;    // over BH/4
        float4 xv = x[i], sv = sx[i];
        int h = (int)((i * 4) & (HDIM - 1));
        float4 kmv = *(const float4*)(km + h);
        float4 vmv = *(const float4*)(vm + h);
        float4 rmv = *(const float4*)(rm + h);
        if (do_copy) out_x[i] = xv;
        half_store4(0, i,
            fmaf(kmv.x, xv.x - sv.x, sv.x), fmaf(kmv.y, xv.y - sv.y, sv.y),
            fmaf(kmv.z, xv.z - sv.z, sv.z), fmaf(kmv.w, xv.w - sv.w, sv.w));
        half_store4(1, i,
            fmaf(vmv.x, xv.x - sv.x, sv.x), fmaf(vmv.y, xv.y - sv.y, sv.y),
            fmaf(vmv.z, xv.z - sv.z, sv.z), fmaf(vmv.w, xv.w - sv.w, sv.w));
        half_store4(2, i,
            fmaf(rmv.x, xv.x - sv.x, sv.x), fmaf(rmv.y, xv.y - sv.y, sv.y),
            fmaf(rmv.z, xv.z - sv.z, sv.z), fmaf(rmv.w, xv.w - sv.w, sv.w));
    }
}

// ============================================================================
// WKV elementwise
// ============================================================================
__device__ __forceinline__ void wkv_comp(float k, float v, float rl,
                                         float A, float Bv, float P,
                                         float tfv, float tdv,
                                         float& aa, float& bb, float& p2o, float& g)
{
    float r = 1.0f / (1.0f + expf(-rl));
    float w = k + tfv;
    float p = fmaxf(P, w);
    float e1 = expf(P - p), e2 = expf(w - p);
    float wkv = (e1 * A + e2 * v) / (e1 * Bv + e2);
    float w2 = P + tdv;
    p2o = fmaxf(w2, k);
    float ea = expf(w2 - p2o), eb = expf(k - p2o);
    aa = ea * A + eb * v;
    bb = ea * Bv + eb;
    g = r * wkv;
}

__global__ void wkv_kernel(const float4* __restrict__ sa, const float4* __restrict__ sb,
                           const float4* __restrict__ sp, const float* __restrict__ td,
                           const float* __restrict__ tf, float* __restrict__ out,
                           int nslots)
{
    size_t i = (size_t)blockIdx.x * blockDim.x + threadIdx.x;    // over BH/4
    int h = (int)((i * 4) & (HDIM - 1));
    const float4* lin = (const float4*)g_lin;
    float4 k4 = lin[i];
    float4 v4 = lin[BH_ / 4 + i];
    float4 r4 = lin[2 * (BH_ / 4) + i];
    float4 sa4 = sa[i], sb4 = sb[i], sp4 = sp[i];
    float4 tf4 = *(const float4*)(tf + h);
    float4 td4 = *(const float4*)(td + h);

    float4 aa4, bb4, p24;
    float g0, g1, g2, g3;
    wkv_comp(k4.x, v4.x, r4.x, sa4.x, sb4.x, sp4.x, tf4.x, td4.x, aa4.x, bb4.x, p24.x, g0);
    wkv_comp(k4.y, v4.y, r4.y, sa4.y, sb4.y, sp4.y, tf4.y, td4.y, aa4.y, bb4.y, p24.y, g1);
    wkv_comp(k4.z, v4.z, r4.z, sa4.z, sb4.z, sp4.z, tf4.z, td4.z, aa4.z, bb4.z, p24.z, g2);
    wkv_comp(k4.w, v4.w, r4.w, sa4.w, sb4.w, sp4.w, tf4.w, td4.w, aa4.w, bb4.w, p24.w, g3);

    if (nslots > 2) ((float4*)(out + 2 * BH_))[i] = aa4;
    if (nslots > 3) ((float4*)(out + 3 * BH_))[i] = bb4;
    if (nslots > 4) ((float4*)(out + 4 * BH_))[i] = p24;
    half_store4(3, i, g0, g1, g2, g3);
}

// ============================================================================
// Launch (serial r7 schedule — co-tenancy with the GEMM measurably loses)
// ============================================================================
extern "C" void kernel_launch(void* const* d_in, const int* in_sizes, int n_in,
                              void* d_out, int out_size)
{
    const float* x  = (const float*)d_in[0];
    const float* sx = (const float*)d_in[1];
    const float* sa = (const float*)d_in[2];
    const float* sb = (const float*)d_in[3];
    const float* sp = (const float*)d_in[4];
    const float* td = (const float*)d_in[5];
    const float* tf = (const float*)d_in[6];
    const float* km = (const float*)d_in[7];
    const float* vm = (const float*)d_in[8];
    const float* rm = (const float*)d_in[9];
    const float* Wk = (const float*)d_in[10];
    const float* Wv = (const float*)d_in[11];
    const float* Wr = (const float*)d_in[12];
    const float* Wo = (const float*)d_in[13];
    float* out = (float*)d_out;
    const int nslots = (int)((size_t)out_size / BH_);

    cudaFuncSetAttribute(hgemm_kernel,
                         cudaFuncAttributeMaxDynamicSharedMemorySize, GSMEM);

    // 1) Fused prep: weight transpose+convert AND token-shift mixing
    prep_kernel<<<WSPLIT_BLOCKS + MIX_BLOCKS, 256>>>(
        Wk, Wv, Wr, Wo, (const float4*)x, (const float4*)sx, km, vm, rm,
        (float4*)(out + BH_), nslots > 1 ? 1 : 0);

    // 2) k, v, r_linear GEMMs (z = 0,1,2)
    hgemm_kernel<<<dim3(HDIM / BN, BDIM / BM, 3), GTHREADS, GSMEM>>>(nullptr, 0);

    // 3) WKV elementwise: aa/bb/p2 outputs + g = sigmoid(r)*wkv
    wkv_kernel<<<(unsigned)(BH_ / 4 / 256), 256>>>(
        (const float4*)sa, (const float4*)sb, (const float4*)sp, td, tf, out, nslots);

    // 4) out = g @ output_weight
    hgemm_kernel<<<dim3(HDIM / BN, BDIM / BM, 1), GTHREADS, GSMEM>>>(out, 1);
}